// round 10
// baseline (speedup 1.0000x reference)
#include <cuda_runtime.h>
#include <cuda_bf16.h>
#include <cstdint>

typedef unsigned long long ull;

// Problem constants
#define T_STEPS 2048
#define R_DIM   1024
#define B_DIM   8
#define H_DIM   256
#define I_DIM   128

#define NCTA 128
#define NTHR 256

// ---------------------------------------------------------------------------
// Device-global scratch
// ---------------------------------------------------------------------------
__device__ float    g_uin[(size_t)T_STEPS * R_DIM * B_DIM];  // [t][r][b]
__device__ float    g_x[2][R_DIM * B_DIM];                   // [buf][r*8+b]
__device__ float    g_p[2][B_DIM * H_DIM];                   // [buf][b*H+h]
__device__ float    g_h[2][B_DIM * H_DIM];                   // [buf][b*H+h]
__device__ unsigned g_sync[NCTA * 32];                       // per-CTA flag, own 128B line

// ---------------------------------------------------------------------------
// Relaxed-strong (GPU-scope, L2-coherent, L1-bypassing, NO fence) helpers.
// ---------------------------------------------------------------------------
__device__ __forceinline__ unsigned ld_rx_u32(const unsigned* p) {
    unsigned v;
    asm volatile("ld.relaxed.gpu.global.u32 %0, [%1];" : "=r"(v) : "l"(p) : "memory");
    return v;
}
__device__ __forceinline__ void st_rx_u32(unsigned* p, unsigned v) {
    asm volatile("st.relaxed.gpu.global.u32 [%0], %1;" :: "l"(p), "r"(v) : "memory");
}
__device__ __forceinline__ float ld_rx_f32(const float* p) {
    float v;
    asm volatile("ld.relaxed.gpu.global.f32 %0, [%1];" : "=f"(v) : "l"(p) : "memory");
    return v;
}
__device__ __forceinline__ void st_rx_f32(float* p, float v) {
    asm volatile("st.relaxed.gpu.global.f32 [%0], %1;" :: "l"(p), "f"(v) : "memory");
}
__device__ __forceinline__ void ld_rx_v2u64(const ull* p, ull& a, ull& b) {
    asm volatile("ld.relaxed.gpu.global.v2.u64 {%0,%1}, [%2];"
                 : "=l"(a), "=l"(b) : "l"(p) : "memory");
}

// ---------------------------------------------------------------------------
// Packed f32x2 helpers (Blackwell FFMA2 path — PTX only)
// ---------------------------------------------------------------------------
__device__ __forceinline__ ull f32x2_fma(ull a, ull b, ull c) {
    ull d;
    asm("fma.rn.f32x2 %0, %1, %2, %3;" : "=l"(d) : "l"(a), "l"(b), "l"(c));
    return d;
}
__device__ __forceinline__ ull f32x2_add(ull a, ull b) {
    ull d;
    asm("add.rn.f32x2 %0, %1, %2;" : "=l"(d) : "l"(a), "l"(b));
    return d;
}
__device__ __forceinline__ ull pack_dup(float w) {
    unsigned u = __float_as_uint(w);
    return ((ull)u << 32) | (ull)u;
}

// ---------------------------------------------------------------------------
// Packed butterfly reduction on f32x2 values.
// ---------------------------------------------------------------------------
template <int N>
__device__ __forceinline__ void butterfly_reduce2(ull* acc, unsigned lane) {
    int n = N;
#pragma unroll
    for (int off = 16; off >= 1; off >>= 1) {
        if (n > 1) {
            const int h = n >> 1;
            const bool up = (lane & off) != 0;
#pragma unroll
            for (int i = 0; i < h; ++i) {
                ull send = up ? acc[i] : acc[i + h];
                ull recv = __shfl_xor_sync(0xffffffffu, send, off);
                if (up) acc[i + h] = f32x2_add(acc[i + h], recv);
                else    acc[i]     = f32x2_add(acc[i], recv);
            }
            if (up) {
#pragma unroll
                for (int i = 0; i < h; ++i) acc[i] = acc[i + h];
            }
            n = h;
        } else {
            acc[0] = f32x2_add(acc[0], __shfl_xor_sync(0xffffffffu, acc[0], off));
        }
    }
}

// ---------------------------------------------------------------------------
// Kernel A: uin[t][r][b] = u[b][t][:] . w_in[r][:] + w_bias[r]
// ---------------------------------------------------------------------------
#define UIN_WPAD 132
#define UIN_SMEM (256 * UIN_WPAD * 4 + B_DIM * I_DIM * 4)

__global__ void __launch_bounds__(256) uin_kernel(
    const float* __restrict__ u, const float* __restrict__ w_in,
    const float* __restrict__ w_bias)
{
    extern __shared__ float sm[];
    float* w_s = sm;
    float* u_s = sm + 256 * UIN_WPAD;

    const int tid = threadIdx.x;
    const int r0  = blockIdx.x * 256;
    const int t0  = blockIdx.y * 64;

    for (int j = tid; j < 256 * I_DIM; j += 256) {
        int row = j >> 7, i = j & 127;
        w_s[row * UIN_WPAD + i] = w_in[(r0 + row) * I_DIM + i];
    }
    const float bias = w_bias[r0 + tid];

    for (int tt = 0; tt < 64; ++tt) {
        const int t = t0 + tt;
        __syncthreads();
        for (int j = tid; j < B_DIM * I_DIM; j += 256) {
            int b = j >> 7, i = j & 127;
            u_s[j] = u[((size_t)b * T_STEPS + t) * I_DIM + i];
        }
        __syncthreads();

        float acc[B_DIM];
#pragma unroll
        for (int b = 0; b < B_DIM; ++b) acc[b] = bias;

        const float4* wrow = reinterpret_cast<const float4*>(&w_s[tid * UIN_WPAD]);
#pragma unroll 8
        for (int i4 = 0; i4 < I_DIM / 4; ++i4) {
            float4 w4 = wrow[i4];
#pragma unroll
            for (int b = 0; b < B_DIM; ++b) {
                float4 u4 = reinterpret_cast<const float4*>(&u_s[b * I_DIM])[i4];
                acc[b] = fmaf(w4.x, u4.x, acc[b]);
                acc[b] = fmaf(w4.y, u4.y, acc[b]);
                acc[b] = fmaf(w4.z, u4.z, acc[b]);
                acc[b] = fmaf(w4.w, u4.w, acc[b]);
            }
        }
        float* dst = &g_uin[((size_t)t * R_DIM + r0 + tid) * B_DIM];
        reinterpret_cast<float4*>(dst)[0] = make_float4(acc[0], acc[1], acc[2], acc[3]);
        reinterpret_cast<float4*>(dst)[1] = make_float4(acc[4], acc[5], acc[6], acc[7]);
    }
}

// ---------------------------------------------------------------------------
// Kernel B: persistent fused recurrence; relaxed-strong dataflow barrier.
// Iteration k: MAC(x_k, p_{k-1}) -> publish via st.relaxed + readback ->
//   flag[cta] = epoch + OR(readback deps)>>31 (dataflow-ordered) ->
//   all-to-all poll (tid<128, one flag each) -> syncthreads -> gate(t=k-1).
// NO fences, NO acquire/release, NO atomics.
// ---------------------------------------------------------------------------
#define SM_W2    0
#define SM_WP2   (8 * 1024)
#define SM_RED   (SM_WP2 + 2 * 1024)
#define SM_REDP  (SM_RED + 256)
#define SM_ULLS  (SM_REDP + 64)
// deps region: 96 u32 (depx[64], depp[16], deph[16]), 16B aligned
#define ESN_SMEM (SM_ULLS * 8 + (512 + 512 + 2) * 4 + 96 * 4 + 8)

__global__ void __launch_bounds__(NTHR, 1) esn_persistent(
    const float* __restrict__ w,
    const float* __restrict__ w_pca,
    const float* __restrict__ wzp,
    const float* __restrict__ wzh,
    const float* __restrict__ bz,
    float* __restrict__ out)
{
    extern __shared__ ull smu[];
    ull* w2    = smu + SM_W2;
    ull* wp2   = smu + SM_WP2;
    ull* red2  = smu + SM_RED;
    ull* redp2 = smu + SM_REDP;
    float* wzp_s = (float*)(smu + SM_ULLS);
    float* wzh_s = wzp_s + 512;
    float* bz_s  = wzh_s + 512;
    unsigned* deps = (unsigned*)(((size_t)(bz_s + 2) + 15) & ~(size_t)15);
    unsigned* depx = deps;          // [64]
    unsigned* depp = deps + 64;     // [16]
    unsigned* deph = deps + 80;     // [16]
    float* redf  = (float*)red2;
    float* redpf = (float*)redp2;

    const int tid  = threadIdx.x;
    const int cta  = blockIdx.x;
    const int warp = tid >> 5;
    const unsigned lane = tid & 31;

    // One-time weight staging (duplicated pairs for f32x2)
    for (int j = tid; j < 8 * R_DIM; j += NTHR)
        w2[j] = pack_dup(w[(size_t)cta * 8 * R_DIM + j]);
    for (int j = tid; j < 2 * R_DIM; j += NTHR) {
        int hh = j >> 10, r = j & (R_DIM - 1);
        wp2[j] = pack_dup(w_pca[(size_t)r * H_DIM + cta * 2 + hh]);
    }
    for (int j = tid; j < 2 * H_DIM; j += NTHR) {
        int hi = j >> 8, hq = j & (H_DIM - 1);
        wzp_s[j] = wzp[(cta * 2 + hi) * H_DIM + hq];
        wzh_s[j] = wzh[(cta * 2 + hi) * H_DIM + hq];
    }
    if (tid < 2) bz_s[tid] = bz[cta * 2 + tid];
    if (tid < 96) deps[tid] = 0;
    __syncthreads();

    for (int k = 0; k <= T_STEPS; ++k) {
        const bool do_res = (k < T_STEPS);
        const bool do_pca = (k >= 1);

        // ---- uin prefetch (cold DRAM; written by kernel A, no coherence issue)
        float uin_pref = 0.f;
        if (do_res && tid < 64)
            uin_pref = __ldcg(&g_uin[(size_t)k * 8192 + cta * 64 + tid]);

        // ---- MAC phase: x loads relaxed-strong (L1-bypassing) ----
        ull racc[32];
        ull pacc[8];
#pragma unroll
        for (int i = 0; i < 32; ++i) racc[i] = 0ull;
#pragma unroll
        for (int i = 0; i < 8; ++i) pacc[i] = 0ull;

        if (do_pca) {
            const ull* xo = (const ull*)g_x[(k + 1) & 1];  // x_{k-1}
#pragma unroll
            for (int c = 0; c < 4; ++c) {
                const int r = warp * 128 + c * 32 + (int)lane;
                ull xv[4];
                ld_rx_v2u64(xo + (size_t)r * 4,     xv[0], xv[1]);
                ld_rx_v2u64(xo + (size_t)r * 4 + 2, xv[2], xv[3]);
                if (do_res) {
#pragma unroll
                    for (int row = 0; row < 8; ++row) {
                        const ull wpp = w2[row * R_DIM + r];
#pragma unroll
                        for (int bp = 0; bp < 4; ++bp)
                            racc[row * 4 + bp] = f32x2_fma(wpp, xv[bp], racc[row * 4 + bp]);
                    }
                }
#pragma unroll
                for (int hh = 0; hh < 2; ++hh) {
                    const ull wpp = wp2[hh * R_DIM + r];
#pragma unroll
                    for (int bp = 0; bp < 4; ++bp)
                        pacc[hh * 4 + bp] = f32x2_fma(wpp, xv[bp], pacc[hh * 4 + bp]);
                }
            }
        }

        // ---- intra-warp reductions + scratch stores ----
        if (do_res) {
            butterfly_reduce2<32>(racc, lane);
            red2[warp * 32 + lane] = racc[0];
        }
        if (do_pca) {
            butterfly_reduce2<8>(pacc, lane);
            if ((lane & 3) == 0) redp2[warp * 8 + (lane >> 2)] = pacc[0];
        }
        __syncthreads();

        // ---- finalize: publish state via st.relaxed, READBACK for ordering --
        if (do_res && tid < 64) {
            float s = 0.f;
#pragma unroll
            for (int wj = 0; wj < 8; ++wj) s += redf[wj * 64 + tid];
            const float val = tanhf(uin_pref + s);
            float* dst = &g_x[k & 1][cta * 64 + tid];
            st_rx_f32(dst, val);
            depx[tid] = ld_rx_u32((const unsigned*)dst) ^ __float_as_uint(val); // 0
        }
        if (do_pca && tid < 16) {
            float s = 0.f;
#pragma unroll
            for (int wj = 0; wj < 8; ++wj) s += redpf[wj * 16 + tid];
            const int h = cta * 2 + (tid >> 3);
            const int b = tid & 7;
            float* dst = &g_p[(k - 1) & 1][b * H_DIM + h];
            st_rx_f32(dst, s);
            depp[tid] = ld_rx_u32((const unsigned*)dst) ^ __float_as_uint(s);   // 0
        }
        __syncthreads();   // deps visible to tid0; also x/p readbacks done

        // ---- flag: value carries readback deps (x, p, prev-iteration h) ----
        const unsigned epoch = (unsigned)(k + 1);
        if (tid == 0) {
            unsigned d = 0;
            const uint4* dv = (const uint4*)deps;
#pragma unroll
            for (int i = 0; i < 24; ++i) {
                uint4 q = dv[i];
                d |= q.x | q.y | q.z | q.w;
            }
            st_rx_u32(&g_sync[cta * 32], epoch + (d >> 31));   // = epoch
        }
        // ---- all-to-all: each of 128 threads polls one CTA's flag ----
        if (tid < NCTA) {
            const unsigned* fp = &g_sync[tid * 32];
            unsigned v;
            do { v = ld_rx_u32(fp); } while (v < epoch);
        }
        __syncthreads();   // all polls complete before any post-barrier load

        // ---- gate for t = k-1 (post-barrier; all loads relaxed-strong) ----
        if (k >= 1) {
            const int t = k - 1;
            const float* p  = g_p[t & 1];
            const float* hp = g_h[(t + 1) & 1];
            const bool have_h = (t > 0);
            const int b = warp;

            float sacc0 = 0.f, sacc1 = 0.f;
#pragma unroll
            for (int c = 0; c < 8; ++c) {
                const int hq = c * 32 + (int)lane;
                const float pv = ld_rx_f32(&p[b * H_DIM + hq]);
                const float hv = have_h ? ld_rx_f32(&hp[b * H_DIM + hq]) : 0.f;
                sacc0 = fmaf(pv, wzp_s[hq],         fmaf(hv, wzh_s[hq],         sacc0));
                sacc1 = fmaf(pv, wzp_s[H_DIM + hq], fmaf(hv, wzh_s[H_DIM + hq], sacc1));
            }
#pragma unroll
            for (int off = 16; off >= 1; off >>= 1) {
                sacc0 += __shfl_xor_sync(0xffffffffu, sacc0, off);
                sacc1 += __shfl_xor_sync(0xffffffffu, sacc1, off);
            }
            if (lane < 2) {
                const int h = cta * 2 + (int)lane;
                const float s = (lane == 0 ? sacc0 : sacc1) + bz_s[lane];
                const float z = 1.f / (1.f + __expf(-s));
                const float hv = have_h ? ld_rx_f32(&hp[b * H_DIM + h]) : 0.f;
                const float pv = ld_rx_f32(&p[b * H_DIM + h]);
                const float hn = (1.f - z) * hv + z * pv;
                float* dst = &g_h[t & 1][b * H_DIM + h];
                st_rx_f32(dst, hn);
                deph[warp * 2 + lane] =
                    ld_rx_u32((const unsigned*)dst) ^ __float_as_uint(hn);      // 0
                out[((size_t)b * T_STEPS + t) * H_DIM + h] = hn;
            }
        }
        // deph ordered before tid0's next read by the post-reduce syncthreads
    }
}

// ---------------------------------------------------------------------------
// Launch
// ---------------------------------------------------------------------------
extern "C" void kernel_launch(void* const* d_in, const int* in_sizes, int n_in,
                              void* d_out, int out_size) {
    const float* u      = (const float*)d_in[0];
    const float* w_in   = (const float*)d_in[1];
    const float* w      = (const float*)d_in[2];
    const float* w_bias = (const float*)d_in[3];
    const float* w_pca  = (const float*)d_in[4];
    const float* wzp    = (const float*)d_in[5];
    const float* wzh    = (const float*)d_in[6];
    const float* bz     = (const float*)d_in[7];
    float* out = (float*)d_out;

    // Reset flags every call (captured into the graph).
    void* sync_addr = nullptr;
    cudaGetSymbolAddress(&sync_addr, g_sync);
    cudaMemsetAsync(sync_addr, 0, sizeof(unsigned) * NCTA * 32);

    cudaFuncSetAttribute(uin_kernel,
                         cudaFuncAttributeMaxDynamicSharedMemorySize, UIN_SMEM);
    uin_kernel<<<dim3(4, 32), 256, UIN_SMEM>>>(u, w_in, w_bias);

    cudaFuncSetAttribute(esn_persistent,
                         cudaFuncAttributeMaxDynamicSharedMemorySize, ESN_SMEM);
    esn_persistent<<<NCTA, NTHR, ESN_SMEM>>>(w, w_pca, wzp, wzh, bz, out);
}

// round 12
// speedup vs baseline: 3.2568x; 3.2568x over previous
#include <cuda_runtime.h>
#include <cuda_bf16.h>
#include <cstdint>

// Problem constants
#define T_STEPS 2048
#define R_DIM   1024
#define B_DIM   8
#define H_DIM   256
#define I_DIM   128
#define NTHR    256

__device__ float g_uin[(size_t)T_STEPS * R_DIM * B_DIM];   // [t][r][b]

// ---------------------------------------------------------------------------
// Helpers
// ---------------------------------------------------------------------------
__device__ __forceinline__ uint32_t smem_u32(const void* p) {
    uint32_t a;
    asm("{ .reg .u64 t; cvta.to.shared.u64 t, %1; cvt.u32.u64 %0, t; }"
        : "=r"(a) : "l"(p));
    return a;
}
__device__ __forceinline__ void st_cluster_f32(uint32_t laddr, int rank, float v) {
    uint32_t rem;
    asm volatile("mapa.shared::cluster.u32 %0, %1, %2;"
                 : "=r"(rem) : "r"(laddr), "r"(rank));
    asm volatile("st.shared::cluster.f32 [%0], %1;" :: "r"(rem), "f"(v) : "memory");
}

__host__ __device__ constexpr int ilog2c(int n) {
    return n <= 1 ? 0 : 1 + ilog2c(n / 2);
}

// Butterfly reduction of N per-thread values across 32 lanes.
// Post: lane l holds the full sum of value index v = l >> log2(32/N)
// (each value duplicated across 32/N consecutive lanes).
template <int N>
__device__ __forceinline__ void butterfly_reduce(float* acc, int lane) {
    int n = N;
#pragma unroll
    for (int off = 16; off >= 1; off >>= 1) {
        if (n > 1) {
            const int h = n >> 1;
            const bool up = (lane & off) != 0;
#pragma unroll
            for (int i = 0; i < h; ++i) {
                float send = up ? acc[i] : acc[i + h];
                float recv = __shfl_xor_sync(0xffffffffu, send, off);
                if (up) acc[i + h] += recv; else acc[i] += recv;
            }
            if (up) {
#pragma unroll
                for (int i = 0; i < h; ++i) acc[i] = acc[i + h];
            }
            n = h;
        } else {
            acc[0] += __shfl_xor_sync(0xffffffffu, acc[0], off);
        }
    }
}

// ---------------------------------------------------------------------------
// Kernel A: uin[t][r][b] = u[b][t][:] . w_in[r][:] + w_bias[r]
// ---------------------------------------------------------------------------
#define UIN_WPAD 132
#define UIN_SMEM (256 * UIN_WPAD * 4 + B_DIM * I_DIM * 4)

__global__ void __launch_bounds__(256) uin_kernel(
    const float* __restrict__ u, const float* __restrict__ w_in,
    const float* __restrict__ w_bias)
{
    extern __shared__ float sm[];
    float* w_s = sm;
    float* u_s = sm + 256 * UIN_WPAD;

    const int tid = threadIdx.x;
    const int r0  = blockIdx.x * 256;
    const int t0  = blockIdx.y * 64;

    for (int j = tid; j < 256 * I_DIM; j += 256) {
        int row = j >> 7, i = j & 127;
        w_s[row * UIN_WPAD + i] = w_in[(r0 + row) * I_DIM + i];
    }
    const float bias = w_bias[r0 + tid];

    for (int tt = 0; tt < 64; ++tt) {
        const int t = t0 + tt;
        __syncthreads();
        for (int j = tid; j < B_DIM * I_DIM; j += 256) {
            int b = j >> 7, i = j & 127;
            u_s[j] = u[((size_t)b * T_STEPS + t) * I_DIM + i];
        }
        __syncthreads();

        float acc[B_DIM];
#pragma unroll
        for (int b = 0; b < B_DIM; ++b) acc[b] = bias;

        const float4* wrow = reinterpret_cast<const float4*>(&w_s[tid * UIN_WPAD]);
#pragma unroll 8
        for (int i4 = 0; i4 < I_DIM / 4; ++i4) {
            float4 w4 = wrow[i4];
#pragma unroll
            for (int b = 0; b < B_DIM; ++b) {
                float4 u4 = reinterpret_cast<const float4*>(&u_s[b * I_DIM])[i4];
                acc[b] = fmaf(w4.x, u4.x, acc[b]);
                acc[b] = fmaf(w4.y, u4.y, acc[b]);
                acc[b] = fmaf(w4.z, u4.z, acc[b]);
                acc[b] = fmaf(w4.w, u4.w, acc[b]);
            }
        }
        float* dst = &g_uin[((size_t)t * R_DIM + r0 + tid) * B_DIM];
        reinterpret_cast<float4*>(dst)[0] = make_float4(acc[0], acc[1], acc[2], acc[3]);
        reinterpret_cast<float4*>(dst)[1] = make_float4(acc[4], acc[5], acc[6], acc[7]);
    }
}

// ---------------------------------------------------------------------------
// Kernel B: cluster-scoped persistent recurrence. 4 clusters x CS CTAs.
// Cluster g owns batches {2g, 2g+1}. CTA rank owns 1024/CS W rows (streamed
// from L2), 256/CS pca cols + gate rows (SMEM). State exchanged via DSMEM;
// ONE barrier.cluster per step is the only synchronization.
// ---------------------------------------------------------------------------
#define ESN_SMEM_F(CS_) ((4096 + 1024 + 1024 + (H_DIM/(CS_))*1024 + \
                          (H_DIM/(CS_))*256*2 + (H_DIM/(CS_))) * 4)

template <int CS>
__global__ void __launch_bounds__(NTHR, 1) esn_cluster(
    const float* __restrict__ w,
    const float* __restrict__ w_pca,
    const float* __restrict__ wzp,
    const float* __restrict__ wzh,
    const float* __restrict__ bz,
    float* __restrict__ out)
{
    constexpr int ROWS = R_DIM / CS;      // W rows per CTA
    constexpr int RPW  = ROWS / 8;        // rows per warp
    constexpr int HC   = H_DIM / CS;      // pca cols / gate rows per CTA
    constexpr int HCW  = HC / 8;          // per warp
    constexpr int NVX  = RPW * 2;         // MAC values per warp (rows x 2 batches)
    constexpr int SX   = ilog2c(32 / NVX);
    constexpr int NVP  = HCW * 2;
    constexpr int SP   = ilog2c(32 / NVP);

    extern __shared__ float smf[];
    float* x_s    = smf;                    // [2][2][1024] parity, batch, r
    float* p_s    = x_s + 4096;             // [2][2][256]
    float* h_s    = p_s + 1024;             // [2][2][256]
    float* wpca_s = h_s + 1024;             // [HC][1024]  (transposed)
    float* wzp_s  = wpca_s + HC * 1024;     // [HC][256]
    float* wzh_s  = wzp_s + HC * 256;       // [HC][256]
    float* bz_s   = wzh_s + HC * 256;       // [HC]

    const int tid  = threadIdx.x;
    const int warp = tid >> 5;
    const int lane = tid & 31;
    unsigned cr;
    asm("mov.u32 %0, %%cluster_ctarank;" : "=r"(cr));
    const int crank = (int)cr;
    const int g   = blockIdx.x / CS;
    const int b0  = g * 2;
    const int r0  = crank * ROWS;
    const int hc0 = crank * HC;

    // ---- one-time staging ----
    for (int j = tid; j < 6144; j += NTHR) smf[j] = 0.f;   // zero x/p/h buffers
    for (int idx = tid; idx < 1024 * (HC / 4); idx += NTHR) {
        const int r = idx / (HC / 4);
        const int q = idx % (HC / 4);
        const float4 v4 = *reinterpret_cast<const float4*>(
            &w_pca[(size_t)r * H_DIM + hc0 + 4 * q]);
        wpca_s[(4 * q + 0) * 1024 + r] = v4.x;
        wpca_s[(4 * q + 1) * 1024 + r] = v4.y;
        wpca_s[(4 * q + 2) * 1024 + r] = v4.z;
        wpca_s[(4 * q + 3) * 1024 + r] = v4.w;
    }
    for (int j = tid; j < HC * 256; j += NTHR) {
        const int row = j >> 8, q = j & 255;
        wzp_s[j] = wzp[(hc0 + row) * H_DIM + q];
        wzh_s[j] = wzh[(hc0 + row) * H_DIM + q];
    }
    if (tid < HC) bz_s[tid] = bz[hc0 + tid];
    __syncthreads();
    asm volatile("barrier.cluster.arrive.aligned;" ::: "memory");
    asm volatile("barrier.cluster.wait.aligned;"   ::: "memory");

    // ---- main loop: gate(t=k-2) | MAC x_k | pca p_{k-1} | barrier ----
    for (int k = 0; k <= T_STEPS + 1; ++k) {
        const bool do_mac  = (k < T_STEPS);
        const bool do_pca  = (k >= 1 && k <= T_STEPS);
        const bool do_gate = (k >= 2);

        // MAC finalize mapping (also used for uin prefetch)
        const int vx   = lane >> SX;
        const int mrow = vx >> 1;
        const int mb   = vx & 1;
        const int grow = r0 + warp * RPW + mrow;

        float uin_pref = 0.f;
        if (do_mac)
            uin_pref = __ldcg(&g_uin[((size_t)k * R_DIM + grow) * 8 + b0 + mb]);

        // ---- gate for t = k-2 (inputs crossed last step's barrier) ----
        if (do_gate) {
            const int t = k - 2;
            const float* pv = p_s + (t & 1) * 512;
            const float* hv = h_s + ((t + 1) & 1) * 512;
            const bool have_h = (t > 0);

            float ga[NVP];
#pragma unroll
            for (int i = 0; i < NVP; ++i) ga[i] = 0.f;
#pragma unroll
            for (int q = 0; q < 8; ++q) {
                const int j = lane + 32 * q;
                const float pj0 = pv[j],      pj1 = pv[256 + j];
                const float hj0 = have_h ? hv[j] : 0.f;
                const float hj1 = have_h ? hv[256 + j] : 0.f;
#pragma unroll
                for (int rr = 0; rr < HCW; ++rr) {
                    const int row = warp * HCW + rr;
                    const float wp = wzp_s[row * 256 + j];
                    const float wh = wzh_s[row * 256 + j];
                    ga[rr * 2 + 0] = fmaf(pj0, wp, fmaf(hj0, wh, ga[rr * 2 + 0]));
                    ga[rr * 2 + 1] = fmaf(pj1, wp, fmaf(hj1, wh, ga[rr * 2 + 1]));
                }
            }
            butterfly_reduce<NVP>(ga, lane);
            if ((lane & ((1 << SP) - 1)) == 0) {
                const int v   = lane >> SP;
                const int row = warp * HCW + (v >> 1);
                const int b   = v & 1;
                const int hg  = hc0 + row;
                const float s = ga[0] + bz_s[row];
                const float z = 1.f / (1.f + __expf(-s));
                const float po = pv[b * 256 + hg];
                const float ho = have_h ? hv[b * 256 + hg] : 0.f;
                const float hn = (1.f - z) * ho + z * po;
                const uint32_t la = smem_u32(&h_s[(t & 1) * 512 + b * 256 + hg]);
#pragma unroll
                for (int rk = 0; rk < CS; ++rk) st_cluster_f32(la, rk, hn);
                out[((size_t)(b0 + b) * T_STEPS + t) * H_DIM + hg] = hn;
            }
        }

        // ---- load x_{k-1} slice into registers (reused by MAC and pca) ----
        float xv0[32], xv1[32];
        if (do_pca) {
            const float* xb = x_s + ((k + 1) & 1) * 2048;
#pragma unroll
            for (int i = 0; i < 8; ++i) {
                const float4 a = *reinterpret_cast<const float4*>(
                    &xb[4 * lane + 128 * i]);
                const float4 b = *reinterpret_cast<const float4*>(
                    &xb[1024 + 4 * lane + 128 * i]);
                xv0[i * 4 + 0] = a.x; xv0[i * 4 + 1] = a.y;
                xv0[i * 4 + 2] = a.z; xv0[i * 4 + 3] = a.w;
                xv1[i * 4 + 0] = b.x; xv1[i * 4 + 1] = b.y;
                xv1[i * 4 + 2] = b.z; xv1[i * 4 + 3] = b.w;
            }
        }

        // ---- reservoir MAC: ROWS rows x 2 batches, W streamed from L2 ----
        if (do_mac) {
            float acc[NVX];
#pragma unroll
            for (int i = 0; i < NVX; ++i) acc[i] = 0.f;
            if (k >= 1) {
#pragma unroll
                for (int rr = 0; rr < RPW; ++rr) {
                    const float4* wr = reinterpret_cast<const float4*>(
                        w + (size_t)(r0 + warp * RPW + rr) * 1024) + lane;
                    float a0 = 0.f, a1 = 0.f;
#pragma unroll
                    for (int i = 0; i < 8; ++i) {
                        const float4 w4 = __ldcg(wr + 32 * i);
                        a0 = fmaf(w4.x, xv0[4 * i + 0], a0);
                        a0 = fmaf(w4.y, xv0[4 * i + 1], a0);
                        a0 = fmaf(w4.z, xv0[4 * i + 2], a0);
                        a0 = fmaf(w4.w, xv0[4 * i + 3], a0);
                        a1 = fmaf(w4.x, xv1[4 * i + 0], a1);
                        a1 = fmaf(w4.y, xv1[4 * i + 1], a1);
                        a1 = fmaf(w4.z, xv1[4 * i + 2], a1);
                        a1 = fmaf(w4.w, xv1[4 * i + 3], a1);
                    }
                    acc[rr * 2 + 0] = a0;
                    acc[rr * 2 + 1] = a1;
                }
            }
            butterfly_reduce<NVX>(acc, lane);
            if ((lane & ((1 << SX) - 1)) == 0) {
                const float val = tanhf(uin_pref + acc[0]);
                const uint32_t la = smem_u32(
                    &x_s[(k & 1) * 2048 + mb * 1024 + grow]);
#pragma unroll
                for (int rk = 0; rk < CS; ++rk) st_cluster_f32(la, rk, val);
            }
        }

        // ---- pca p_{k-1} = x_{k-1} . wpca (SMEM-cached, transposed) ----
        if (do_pca) {
            float pa[NVP];
#pragma unroll
            for (int i = 0; i < NVP; ++i) pa[i] = 0.f;
#pragma unroll
            for (int cc = 0; cc < HCW; ++cc) {
                const float* wc = wpca_s + (warp * HCW + cc) * 1024;
                float a0 = 0.f, a1 = 0.f;
#pragma unroll
                for (int i = 0; i < 8; ++i) {
                    const float4 w4 = *reinterpret_cast<const float4*>(
                        &wc[4 * lane + 128 * i]);
                    a0 = fmaf(w4.x, xv0[4 * i + 0], a0);
                    a0 = fmaf(w4.y, xv0[4 * i + 1], a0);
                    a0 = fmaf(w4.z, xv0[4 * i + 2], a0);
                    a0 = fmaf(w4.w, xv0[4 * i + 3], a0);
                    a1 = fmaf(w4.x, xv1[4 * i + 0], a1);
                    a1 = fmaf(w4.y, xv1[4 * i + 1], a1);
                    a1 = fmaf(w4.z, xv1[4 * i + 2], a1);
                    a1 = fmaf(w4.w, xv1[4 * i + 3], a1);
                }
                pa[cc * 2 + 0] = a0;
                pa[cc * 2 + 1] = a1;
            }
            butterfly_reduce<NVP>(pa, lane);
            if ((lane & ((1 << SP) - 1)) == 0) {
                const int v   = lane >> SP;
                const int col = warp * HCW + (v >> 1);
                const int b   = v & 1;
                const int hg  = hc0 + col;
                const uint32_t la = smem_u32(
                    &p_s[((k - 1) & 1) * 512 + b * 256 + hg]);
#pragma unroll
                for (int rk = 0; rk < CS; ++rk) st_cluster_f32(la, rk, pa[0]);
            }
        }

        // ---- the ONLY sync: cluster barrier (release/acquire, same-die) ----
        asm volatile("barrier.cluster.arrive.aligned;" ::: "memory");
        asm volatile("barrier.cluster.wait.aligned;"   ::: "memory");
    }
}

// ---------------------------------------------------------------------------
// Launch: pick cluster size 16 if the HW/driver allows, else portable 8.
// ---------------------------------------------------------------------------
extern "C" void kernel_launch(void* const* d_in, const int* in_sizes, int n_in,
                              void* d_out, int out_size) {
    const float* u      = (const float*)d_in[0];
    const float* w_in   = (const float*)d_in[1];
    const float* w      = (const float*)d_in[2];
    const float* w_bias = (const float*)d_in[3];
    const float* w_pca  = (const float*)d_in[4];
    const float* wzp    = (const float*)d_in[5];
    const float* wzh    = (const float*)d_in[6];
    const float* bz     = (const float*)d_in[7];
    float* out = (float*)d_out;

    cudaFuncSetAttribute(uin_kernel,
                         cudaFuncAttributeMaxDynamicSharedMemorySize, UIN_SMEM);
    uin_kernel<<<dim3(4, 32), 256, UIN_SMEM>>>(u, w_in, w_bias);

    // Probe 16-CTA cluster support (deterministic per device).
    cudaFuncSetAttribute(esn_cluster<16>,
                         cudaFuncAttributeMaxDynamicSharedMemorySize,
                         ESN_SMEM_F(16));
    cudaFuncSetAttribute(esn_cluster<16>,
                         cudaFuncAttributeNonPortableClusterSizeAllowed, 1);
    cudaFuncSetAttribute(esn_cluster<8>,
                         cudaFuncAttributeMaxDynamicSharedMemorySize,
                         ESN_SMEM_F(8));

    int maxc = 0;
    {
        cudaLaunchConfig_t probe = {};
        probe.gridDim  = {64, 1, 1};
        probe.blockDim = {NTHR, 1, 1};
        probe.dynamicSmemBytes = ESN_SMEM_F(16);
        cudaError_t e = cudaOccupancyMaxPotentialClusterSize(
            &maxc, (const void*)esn_cluster<16>, &probe);
        if (e != cudaSuccess) { maxc = 0; cudaGetLastError(); }
    }

    cudaLaunchAttribute attrs[1];
    attrs[0].id = cudaLaunchAttributeClusterDimension;
    cudaLaunchConfig_t cfg = {};
    cfg.blockDim = {NTHR, 1, 1};
    cfg.attrs    = attrs;
    cfg.numAttrs = 1;

    if (maxc >= 16) {
        attrs[0].val.clusterDim = {16, 1, 1};
        cfg.gridDim  = {64, 1, 1};
        cfg.dynamicSmemBytes = ESN_SMEM_F(16);
        cudaLaunchKernelEx(&cfg, esn_cluster<16>, w, w_pca, wzp, wzh, bz, out);
    } else {
        attrs[0].val.clusterDim = {8, 1, 1};
        cfg.gridDim  = {32, 1, 1};
        cfg.dynamicSmemBytes = ESN_SMEM_F(8);
        cudaLaunchKernelEx(&cfg, esn_cluster<8>, w, w_pca, wzp, wzh, bz, out);
    }
}

// round 13
// speedup vs baseline: 3.4918x; 1.0722x over previous
#include <cuda_runtime.h>
#include <cuda_bf16.h>
#include <cstdint>

// Problem constants
#define T_STEPS 2048
#define R_DIM   1024
#define B_DIM   8
#define H_DIM   256
#define I_DIM   128
#define NTHR    256

__device__ float g_uin[(size_t)T_STEPS * R_DIM * B_DIM];   // [t][r][b]

// ---------------------------------------------------------------------------
// Helpers
// ---------------------------------------------------------------------------
__device__ __forceinline__ uint32_t smem_u32(const void* p) {
    uint32_t a;
    asm("{ .reg .u64 t; cvta.to.shared.u64 t, %1; cvt.u32.u64 %0, t; }"
        : "=r"(a) : "l"(p));
    return a;
}
__device__ __forceinline__ void st_cluster_f32(uint32_t laddr, int rank, float v) {
    uint32_t rem;
    asm volatile("mapa.shared::cluster.u32 %0, %1, %2;"
                 : "=r"(rem) : "r"(laddr), "r"(rank));
    asm volatile("st.shared::cluster.f32 [%0], %1;" :: "r"(rem), "f"(v) : "memory");
}

__host__ __device__ constexpr int ilog2c(int n) {
    return n <= 1 ? 0 : 1 + ilog2c(n / 2);
}

// Butterfly reduction of N per-thread values across 32 lanes.
// Post: lane l holds the full sum of value index v = l >> log2(32/N).
template <int N>
__device__ __forceinline__ void butterfly_reduce(float* acc, int lane) {
    int n = N;
#pragma unroll
    for (int off = 16; off >= 1; off >>= 1) {
        if (n > 1) {
            const int h = n >> 1;
            const bool up = (lane & off) != 0;
#pragma unroll
            for (int i = 0; i < h; ++i) {
                float send = up ? acc[i] : acc[i + h];
                float recv = __shfl_xor_sync(0xffffffffu, send, off);
                if (up) acc[i + h] += recv; else acc[i] += recv;
            }
            if (up) {
#pragma unroll
                for (int i = 0; i < h; ++i) acc[i] = acc[i + h];
            }
            n = h;
        } else {
            acc[0] += __shfl_xor_sync(0xffffffffu, acc[0], off);
        }
    }
}

// ---------------------------------------------------------------------------
// Kernel A: uin[t][r][b] = u[b][t][:] . w_in[r][:] + w_bias[r]
// ---------------------------------------------------------------------------
#define UIN_WPAD 132
#define UIN_SMEM (256 * UIN_WPAD * 4 + B_DIM * I_DIM * 4)

__global__ void __launch_bounds__(256) uin_kernel(
    const float* __restrict__ u, const float* __restrict__ w_in,
    const float* __restrict__ w_bias)
{
    extern __shared__ float sm[];
    float* w_s = sm;
    float* u_s = sm + 256 * UIN_WPAD;

    const int tid = threadIdx.x;
    const int r0  = blockIdx.x * 256;
    const int t0  = blockIdx.y * 64;

    for (int j = tid; j < 256 * I_DIM; j += 256) {
        int row = j >> 7, i = j & 127;
        w_s[row * UIN_WPAD + i] = w_in[(r0 + row) * I_DIM + i];
    }
    const float bias = w_bias[r0 + tid];

    for (int tt = 0; tt < 64; ++tt) {
        const int t = t0 + tt;
        __syncthreads();
        for (int j = tid; j < B_DIM * I_DIM; j += 256) {
            int b = j >> 7, i = j & 127;
            u_s[j] = u[((size_t)b * T_STEPS + t) * I_DIM + i];
        }
        __syncthreads();

        float acc[B_DIM];
#pragma unroll
        for (int b = 0; b < B_DIM; ++b) acc[b] = bias;

        const float4* wrow = reinterpret_cast<const float4*>(&w_s[tid * UIN_WPAD]);
#pragma unroll 8
        for (int i4 = 0; i4 < I_DIM / 4; ++i4) {
            float4 w4 = wrow[i4];
#pragma unroll
            for (int b = 0; b < B_DIM; ++b) {
                float4 u4 = reinterpret_cast<const float4*>(&u_s[b * I_DIM])[i4];
                acc[b] = fmaf(w4.x, u4.x, acc[b]);
                acc[b] = fmaf(w4.y, u4.y, acc[b]);
                acc[b] = fmaf(w4.z, u4.z, acc[b]);
                acc[b] = fmaf(w4.w, u4.w, acc[b]);
            }
        }
        float* dst = &g_uin[((size_t)t * R_DIM + r0 + tid) * B_DIM];
        reinterpret_cast<float4*>(dst)[0] = make_float4(acc[0], acc[1], acc[2], acc[3]);
        reinterpret_cast<float4*>(dst)[1] = make_float4(acc[4], acc[5], acc[6], acc[7]);
    }
}

// ---------------------------------------------------------------------------
// Kernel B: cluster-scoped persistent recurrence (R12 WINNER + two changes):
//   1. 4-way split accumulators (FFMA chain 32 -> 8)
//   2. 24 W rows per CTA cached in SMEM (3 per warp); 40 streamed from L2
// ---------------------------------------------------------------------------
#define CPW_OF(CS_)  ((CS_) == 16 ? 3 : 0)
#define ESN_SMEM_F(CS_) ((6144 + CPW_OF(CS_) * 8 * 1024 + (H_DIM/(CS_))*1024 + \
                          (H_DIM/(CS_))*256*2 + (H_DIM/(CS_))) * 4)

// One row x 2 batches dot-product with 4-way split accumulators.
// w4src: float4 lane-strided source (SMEM or global, already lane-offset).
__device__ __forceinline__ void row_mac(
    const float4* w4, const float* xv0, const float* xv1,
    bool from_global, float& out0, float& out1)
{
    float a00 = 0.f, a01 = 0.f, a02 = 0.f, a03 = 0.f;
    float a10 = 0.f, a11 = 0.f, a12 = 0.f, a13 = 0.f;
#pragma unroll
    for (int i = 0; i < 8; ++i) {
        const float4 w = from_global ? __ldcg(w4 + 32 * i) : w4[32 * i];
        a00 = fmaf(w.x, xv0[4 * i + 0], a00);
        a01 = fmaf(w.y, xv0[4 * i + 1], a01);
        a02 = fmaf(w.z, xv0[4 * i + 2], a02);
        a03 = fmaf(w.w, xv0[4 * i + 3], a03);
        a10 = fmaf(w.x, xv1[4 * i + 0], a10);
        a11 = fmaf(w.y, xv1[4 * i + 1], a11);
        a12 = fmaf(w.z, xv1[4 * i + 2], a12);
        a13 = fmaf(w.w, xv1[4 * i + 3], a13);
    }
    out0 = (a00 + a01) + (a02 + a03);
    out1 = (a10 + a11) + (a12 + a13);
}

template <int CS>
__global__ void __launch_bounds__(NTHR, 1) esn_cluster(
    const float* __restrict__ w,
    const float* __restrict__ w_pca,
    const float* __restrict__ wzp,
    const float* __restrict__ wzh,
    const float* __restrict__ bz,
    float* __restrict__ out)
{
    constexpr int ROWS = R_DIM / CS;      // W rows per CTA
    constexpr int RPW  = ROWS / 8;        // rows per warp
    constexpr int CPW  = CPW_OF(CS);      // SMEM-cached rows per warp
    constexpr int HC   = H_DIM / CS;      // pca cols / gate rows per CTA
    constexpr int HCW  = HC / 8;          // per warp
    constexpr int NVX  = RPW * 2;         // MAC values per warp
    constexpr int SX   = ilog2c(32 / NVX);
    constexpr int NVP  = HCW * 2;
    constexpr int SP   = ilog2c(32 / NVP);

    extern __shared__ float smf[];
    float* x_s    = smf;                       // [2][2][1024]
    float* p_s    = x_s + 4096;                // [2][2][256]
    float* h_s    = p_s + 1024;                // [2][2][256]
    float* wc_s   = h_s + 1024;                // [CPW*8][1024] cached W rows
    float* wpca_s = wc_s + CPW * 8 * 1024;     // [HC][1024]  (transposed)
    float* wzp_s  = wpca_s + HC * 1024;        // [HC][256]
    float* wzh_s  = wzp_s + HC * 256;          // [HC][256]
    float* bz_s   = wzh_s + HC * 256;          // [HC]

    const int tid  = threadIdx.x;
    const int warp = tid >> 5;
    const int lane = tid & 31;
    unsigned cr;
    asm("mov.u32 %0, %%cluster_ctarank;" : "=r"(cr));
    const int crank = (int)cr;
    const int g   = blockIdx.x / CS;
    const int b0  = g * 2;
    const int r0  = crank * ROWS;
    const int hc0 = crank * HC;

    // ---- one-time staging ----
    for (int j = tid; j < 6144; j += NTHR) smf[j] = 0.f;   // zero x/p/h buffers
    if (CPW > 0) {
        // cached W rows: rowi = w_*CPW+rr  <-  global row r0 + w_*RPW + rr
        for (int idx = tid; idx < CPW * 8 * 256; idx += NTHR) {
            const int rowi = idx >> 8;
            const int q    = idx & 255;
            const int w_   = rowi / CPW;
            const int rr   = rowi % CPW;
            const float4 v4 = *reinterpret_cast<const float4*>(
                &w[(size_t)(r0 + w_ * RPW + rr) * 1024 + 4 * q]);
            *reinterpret_cast<float4*>(&wc_s[rowi * 1024 + 4 * q]) = v4;
        }
    }
    for (int idx = tid; idx < 1024 * (HC / 4); idx += NTHR) {
        const int r = idx / (HC / 4);
        const int q = idx % (HC / 4);
        const float4 v4 = *reinterpret_cast<const float4*>(
            &w_pca[(size_t)r * H_DIM + hc0 + 4 * q]);
        wpca_s[(4 * q + 0) * 1024 + r] = v4.x;
        wpca_s[(4 * q + 1) * 1024 + r] = v4.y;
        wpca_s[(4 * q + 2) * 1024 + r] = v4.z;
        wpca_s[(4 * q + 3) * 1024 + r] = v4.w;
    }
    for (int j = tid; j < HC * 256; j += NTHR) {
        const int row = j >> 8, q = j & 255;
        wzp_s[j] = wzp[(hc0 + row) * H_DIM + q];
        wzh_s[j] = wzh[(hc0 + row) * H_DIM + q];
    }
    if (tid < HC) bz_s[tid] = bz[hc0 + tid];
    __syncthreads();
    asm volatile("barrier.cluster.arrive.aligned;" ::: "memory");
    asm volatile("barrier.cluster.wait.aligned;"   ::: "memory");

    // ---- main loop: gate(t=k-2) | MAC x_k | pca p_{k-1} | barrier ----
    for (int k = 0; k <= T_STEPS + 1; ++k) {
        const bool do_mac  = (k < T_STEPS);
        const bool do_pca  = (k >= 1 && k <= T_STEPS);
        const bool do_gate = (k >= 2);

        const int vx   = lane >> SX;
        const int mrow = vx >> 1;
        const int mb   = vx & 1;
        const int grow = r0 + warp * RPW + mrow;

        float uin_pref = 0.f;
        if (do_mac)
            uin_pref = __ldcg(&g_uin[((size_t)k * R_DIM + grow) * 8 + b0 + mb]);

        // ---- gate for t = k-2 ----
        if (do_gate) {
            const int t = k - 2;
            const float* pv = p_s + (t & 1) * 512;
            const float* hv = h_s + ((t + 1) & 1) * 512;
            const bool have_h = (t > 0);

            float ga[NVP];
#pragma unroll
            for (int i = 0; i < NVP; ++i) ga[i] = 0.f;
#pragma unroll
            for (int q = 0; q < 8; ++q) {
                const int j = lane + 32 * q;
                const float pj0 = pv[j],      pj1 = pv[256 + j];
                const float hj0 = have_h ? hv[j] : 0.f;
                const float hj1 = have_h ? hv[256 + j] : 0.f;
#pragma unroll
                for (int rr = 0; rr < HCW; ++rr) {
                    const int row = warp * HCW + rr;
                    const float wp = wzp_s[row * 256 + j];
                    const float wh = wzh_s[row * 256 + j];
                    ga[rr * 2 + 0] = fmaf(pj0, wp, fmaf(hj0, wh, ga[rr * 2 + 0]));
                    ga[rr * 2 + 1] = fmaf(pj1, wp, fmaf(hj1, wh, ga[rr * 2 + 1]));
                }
            }
            butterfly_reduce<NVP>(ga, lane);
            if ((lane & ((1 << SP) - 1)) == 0) {
                const int v   = lane >> SP;
                const int row = warp * HCW + (v >> 1);
                const int b   = v & 1;
                const int hg  = hc0 + row;
                const float s = ga[0] + bz_s[row];
                const float z = 1.f / (1.f + __expf(-s));
                const float po = pv[b * 256 + hg];
                const float ho = have_h ? hv[b * 256 + hg] : 0.f;
                const float hn = (1.f - z) * ho + z * po;
                const uint32_t la = smem_u32(&h_s[(t & 1) * 512 + b * 256 + hg]);
#pragma unroll
                for (int rk = 0; rk < CS; ++rk) st_cluster_f32(la, rk, hn);
                out[((size_t)(b0 + b) * T_STEPS + t) * H_DIM + hg] = hn;
            }
        }

        // ---- load x_{k-1} slice into registers ----
        float xv0[32], xv1[32];
        if (do_pca) {
            const float* xb = x_s + ((k + 1) & 1) * 2048;
#pragma unroll
            for (int i = 0; i < 8; ++i) {
                const float4 a = *reinterpret_cast<const float4*>(
                    &xb[4 * lane + 128 * i]);
                const float4 b = *reinterpret_cast<const float4*>(
                    &xb[1024 + 4 * lane + 128 * i]);
                xv0[i * 4 + 0] = a.x; xv0[i * 4 + 1] = a.y;
                xv0[i * 4 + 2] = a.z; xv0[i * 4 + 3] = a.w;
                xv1[i * 4 + 0] = b.x; xv1[i * 4 + 1] = b.y;
                xv1[i * 4 + 2] = b.z; xv1[i * 4 + 3] = b.w;
            }
        }

        // ---- reservoir MAC: CPW cached rows (SMEM) + rest streamed (L2) ----
        if (do_mac) {
            float acc[NVX];
#pragma unroll
            for (int i = 0; i < NVX; ++i) acc[i] = 0.f;
            if (k >= 1) {
#pragma unroll
                for (int rr = 0; rr < CPW; ++rr) {
                    const float4* w4 = reinterpret_cast<const float4*>(
                        &wc_s[(warp * CPW + rr) * 1024]) + lane;
                    row_mac(w4, xv0, xv1, false, acc[rr * 2], acc[rr * 2 + 1]);
                }
#pragma unroll
                for (int rr = CPW; rr < RPW; ++rr) {
                    const float4* w4 = reinterpret_cast<const float4*>(
                        w + (size_t)(r0 + warp * RPW + rr) * 1024) + lane;
                    row_mac(w4, xv0, xv1, true, acc[rr * 2], acc[rr * 2 + 1]);
                }
            }
            butterfly_reduce<NVX>(acc, lane);
            if ((lane & ((1 << SX) - 1)) == 0) {
                const float val = tanhf(uin_pref + acc[0]);
                const uint32_t la = smem_u32(
                    &x_s[(k & 1) * 2048 + mb * 1024 + grow]);
#pragma unroll
                for (int rk = 0; rk < CS; ++rk) st_cluster_f32(la, rk, val);
            }
        }

        // ---- pca p_{k-1} = x_{k-1} . wpca (SMEM, transposed) ----
        if (do_pca) {
            float pa[NVP];
#pragma unroll
            for (int i = 0; i < NVP; ++i) pa[i] = 0.f;
#pragma unroll
            for (int cc = 0; cc < HCW; ++cc) {
                const float4* w4 = reinterpret_cast<const float4*>(
                    &wpca_s[(warp * HCW + cc) * 1024]) + lane;
                row_mac(w4, xv0, xv1, false, pa[cc * 2], pa[cc * 2 + 1]);
            }
            butterfly_reduce<NVP>(pa, lane);
            if ((lane & ((1 << SP) - 1)) == 0) {
                const int v   = lane >> SP;
                const int col = warp * HCW + (v >> 1);
                const int b   = v & 1;
                const int hg  = hc0 + col;
                const uint32_t la = smem_u32(
                    &p_s[((k - 1) & 1) * 512 + b * 256 + hg]);
#pragma unroll
                for (int rk = 0; rk < CS; ++rk) st_cluster_f32(la, rk, pa[0]);
            }
        }

        // ---- the ONLY sync: cluster barrier ----
        asm volatile("barrier.cluster.arrive.aligned;" ::: "memory");
        asm volatile("barrier.cluster.wait.aligned;"   ::: "memory");
    }
}

// ---------------------------------------------------------------------------
// Launch: cluster size 16 if allowed, else portable 8.
// ---------------------------------------------------------------------------
extern "C" void kernel_launch(void* const* d_in, const int* in_sizes, int n_in,
                              void* d_out, int out_size) {
    const float* u      = (const float*)d_in[0];
    const float* w_in   = (const float*)d_in[1];
    const float* w      = (const float*)d_in[2];
    const float* w_bias = (const float*)d_in[3];
    const float* w_pca  = (const float*)d_in[4];
    const float* wzp    = (const float*)d_in[5];
    const float* wzh    = (const float*)d_in[6];
    const float* bz     = (const float*)d_in[7];
    float* out = (float*)d_out;

    cudaFuncSetAttribute(uin_kernel,
                         cudaFuncAttributeMaxDynamicSharedMemorySize, UIN_SMEM);
    uin_kernel<<<dim3(4, 32), 256, UIN_SMEM>>>(u, w_in, w_bias);

    cudaFuncSetAttribute(esn_cluster<16>,
                         cudaFuncAttributeMaxDynamicSharedMemorySize,
                         ESN_SMEM_F(16));
    cudaFuncSetAttribute(esn_cluster<16>,
                         cudaFuncAttributeNonPortableClusterSizeAllowed, 1);
    cudaFuncSetAttribute(esn_cluster<8>,
                         cudaFuncAttributeMaxDynamicSharedMemorySize,
                         ESN_SMEM_F(8));

    int maxc = 0;
    {
        cudaLaunchConfig_t probe = {};
        probe.gridDim  = {64, 1, 1};
        probe.blockDim = {NTHR, 1, 1};
        probe.dynamicSmemBytes = ESN_SMEM_F(16);
        cudaError_t e = cudaOccupancyMaxPotentialClusterSize(
            &maxc, (const void*)esn_cluster<16>, &probe);
        if (e != cudaSuccess) { maxc = 0; cudaGetLastError(); }
    }

    cudaLaunchAttribute attrs[1];
    attrs[0].id = cudaLaunchAttributeClusterDimension;
    cudaLaunchConfig_t cfg = {};
    cfg.blockDim = {NTHR, 1, 1};
    cfg.attrs    = attrs;
    cfg.numAttrs = 1;

    if (maxc >= 16) {
        attrs[0].val.clusterDim = {16, 1, 1};
        cfg.gridDim  = {64, 1, 1};
        cfg.dynamicSmemBytes = ESN_SMEM_F(16);
        cudaLaunchKernelEx(&cfg, esn_cluster<16>, w, w_pca, wzp, wzh, bz, out);
    } else {
        attrs[0].val.clusterDim = {8, 1, 1};
        cfg.gridDim  = {32, 1, 1};
        cfg.dynamicSmemBytes = ESN_SMEM_F(8);
        cudaLaunchKernelEx(&cfg, esn_cluster<8>, w, w_pca, wzp, wzh, bz, out);
    }
}